// round 14
// baseline (speedup 1.0000x reference)
#include <cuda_runtime.h>
#include <cuda_fp16.h>
#include <math.h>
#include <stdint.h>

// Problem constants
#define NSRC 5
#define BATCH 4
#define SEQ 1024
#define DMODEL 768
#define NHEAD 12
#define DHEAD 64

#define QROWS 4096      // B*S
#define KVROWS 20480    // N*B*S

// scale folded into Q projection: 1/sqrt(64) * log2(e)  (softmax done in exp2)
#define QSCALE (0.125f * 1.4426950408889634f)

// Scratch (allocation-free rules: __device__ globals)
__device__ __half g_Xh[(size_t)KVROWS * DMODEL];             // X as fp16
__device__ __half g_Wt[3][(size_t)DMODEL * DMODEL];          // W^T as fp16 [n][k]
__device__ __half g_Qh[(size_t)QROWS * DMODEL];              // Q (pre-scaled)
__device__ __half g_Kh[(size_t)KVROWS * DMODEL];
__device__ __half g_Vh[(size_t)KVROWS * DMODEL];
__device__ float  g_O[(size_t)NSRC * QROWS * DMODEL];        // per-source outputs

// ---------------------------------------------------------------------------
// fp16 m16n8k16, f32 accum. Layouts (g=lane>>2, tig=lane&3):
//   A: a0={(g,2tig),(g,2tig+1)} a1={(g+8,..)} a2={(g,2tig+8..)} a3={(g+8,2tig+8..)}
//   B: b0={(k=2tig,n=g),(k=2tig+1,n=g)} b1={(k=2tig+8..)}
//   C: c0=(g,2tig) c1=(g,2tig+1) c2=(g+8,2tig) c3=(g+8,2tig+1)
__device__ __forceinline__ void mma_f16(float* c, const unsigned* a, const unsigned* b) {
    asm volatile(
        "mma.sync.aligned.m16n8k16.row.col.f32.f16.f16.f32 "
        "{%0,%1,%2,%3}, {%4,%5,%6,%7}, {%8,%9}, {%0,%1,%2,%3};"
        : "+f"(c[0]), "+f"(c[1]), "+f"(c[2]), "+f"(c[3])
        : "r"(a[0]), "r"(a[1]), "r"(a[2]), "r"(a[3]), "r"(b[0]), "r"(b[1]));
}

// fp16 accumulate variant: C packed f16x2, c0={(g,2tig),(g,2tig+1)},
// c1={(g+8,2tig),(g+8,2tig+1)}  (== PV A-frag layout pairing)
__device__ __forceinline__ void mma_f16_h(unsigned* c, const unsigned* a, const unsigned* b) {
    asm volatile(
        "mma.sync.aligned.m16n8k16.row.col.f16.f16.f16.f16 "
        "{%0,%1}, {%2,%3,%4,%5}, {%6,%7}, {%0,%1};"
        : "+r"(c[0]), "+r"(c[1])
        : "r"(a[0]), "r"(a[1]), "r"(a[2]), "r"(a[3]), "r"(b[0]), "r"(b[1]));
}

// packed half2 exp2 (in place)
__device__ __forceinline__ void ex2_h2(unsigned& x) {
    asm("ex2.approx.f16x2 %0, %0;" : "+r"(x));
}

// ldmatrix x4: output reg i <- 8x8 matrix whose row addresses come from
// lanes [8i, 8i+8). Lane-addressing determines the matrix->reg pairing.
__device__ __forceinline__ void ldsm_x4(unsigned* r, uint32_t addr) {
    asm volatile("ldmatrix.sync.aligned.m8n8.x4.shared.b16 {%0,%1,%2,%3}, [%4];"
        : "=r"(r[0]), "=r"(r[1]), "=r"(r[2]), "=r"(r[3]) : "r"(addr));
}
__device__ __forceinline__ void ldsm_x4_t(unsigned* r, uint32_t addr) {
    asm volatile("ldmatrix.sync.aligned.m8n8.x4.trans.shared.b16 {%0,%1,%2,%3}, [%4];"
        : "=r"(r[0]), "=r"(r[1]), "=r"(r[2]), "=r"(r[3]) : "r"(addr));
}

__device__ __forceinline__ void cp_async16(uint32_t dst, const void* src) {
    asm volatile("cp.async.cg.shared.global [%0], [%1], 16;" :: "r"(dst), "l"(src));
}
#define CP_COMMIT() asm volatile("cp.async.commit_group;")
#define CP_WAIT1()  asm volatile("cp.async.wait_group 1;")
#define CP_WAIT0()  asm volatile("cp.async.wait_group 0;")

__device__ __forceinline__ unsigned packh2(float lo, float hi) {
    __half2 h = __floats2half2_rn(lo, hi);
    return *(unsigned*)&h;
}

// ---------------------------------------------------------------------------
// prep_x: fp32 -> fp16 conversion of X
// ---------------------------------------------------------------------------
__global__ void prep_x(const float* __restrict__ X, __half* __restrict__ Xh)
{
    size_t i = ((size_t)blockIdx.x * blockDim.x + threadIdx.x) * 4;
    float4 v = *(const float4*)&X[i];
    __half2 h0 = __floats2half2_rn(v.x, v.y);
    __half2 h1 = __floats2half2_rn(v.z, v.w);
    uint2 u;
    u.x = *(unsigned*)&h0; u.y = *(unsigned*)&h1;
    *(uint2*)&Xh[i] = u;
}

// ---------------------------------------------------------------------------
// prep_w: transpose + convert Wq/Wk/Wv [k][n] f32 -> Wt[z][n][k] fp16
// ---------------------------------------------------------------------------
__global__ void prep_w(const float* __restrict__ Wq, const float* __restrict__ Wk,
                       const float* __restrict__ Wv, __half* __restrict__ Wt)
{
    __shared__ float tile[32][33];
    const float* W = (blockIdx.z == 0) ? Wq : (blockIdx.z == 1) ? Wk : Wv;
    __half* out = Wt + (size_t)blockIdx.z * DMODEL * DMODEL;
    int k0 = blockIdx.y * 32, n0 = blockIdx.x * 32;
    int tx = threadIdx.x, ty = threadIdx.y;
    #pragma unroll
    for (int i = 0; i < 4; i++)
        tile[ty + i * 8][tx] = W[(size_t)(k0 + ty + i * 8) * DMODEL + n0 + tx];
    __syncthreads();
    #pragma unroll
    for (int i = 0; i < 4; i++)
        out[(size_t)(n0 + ty + i * 8) * DMODEL + k0 + tx] =
            __float2half(tile[tx][ty + i * 8]);
}

// ---------------------------------------------------------------------------
// Fused QKV GEMM v3 (fp16 mma, ldmatrix + 3-stage cp.async, ONE barrier/iter)
// C = Xh @ Wt^T + bias. 1D grid of exactly 2112 CTAs (no phantom blocks):
//   id <  192  -> z=0 (Q, 32 y-blocks)
//   id < 1152  -> z=1 (K, 160 y-blocks)
//   else       -> z=2 (V, 160 y-blocks)
// CTA 128m x 128n, BK=64, 8 warps of 32m x 64n. Row stride 36 words.
// ---------------------------------------------------------------------------
#define GS 36   // word stride (144B): ldmatrix rows hit 8 distinct 16B banks
#define GT_W (128 * GS)
#define GSTAGES 3

__global__ __launch_bounds__(256, 2) void gemm_h(
    const __half* __restrict__ Xh, const __half* __restrict__ Wt,
    const float* __restrict__ bq, const float* __restrict__ bk,
    const float* __restrict__ bv,
    __half* __restrict__ Qo, __half* __restrict__ Ko, __half* __restrict__ Vo)
{
    int id = blockIdx.x;
    int z, rem;
    if (id < 192)       { z = 0; rem = id; }
    else if (id < 1152) { z = 1; rem = id - 192; }
    else                { z = 2; rem = id - 1152; }
    const int bx = rem % 6;
    const int by = rem / 6;

    extern __shared__ unsigned gsm[];
    const uint32_t smem_b = (uint32_t)__cvta_generic_to_shared(gsm);
    const uint32_t stage_bytes = 2 * GT_W * 4;

    const __half* Wz = Wt + (size_t)z * DMODEL * DMODEL;
    const float* bias = (z == 0) ? bq : (z == 1) ? bk : bv;
    __half* out = (z == 0) ? Qo : (z == 1) ? Ko : Vo;
    const float scale = (z == 0) ? QSCALE : 1.0f;

    const int tid = threadIdx.x;
    const int lane = tid & 31;
    const int w = tid >> 5;
    const int wm = (w & 3) * 32;
    const int wn = (w >> 2) * 64;
    const int row0 = by * 128;
    const int col0 = bx * 128;

    // A-operand (row varies first):
    const int arow = (lane & 15);
    const int acol8 = (lane >> 4) << 3;
    // B-operand non-trans (col-half varies before row-half):
    const int krow = (lane & 7) + ((lane >> 4) << 3);
    const int kcol8 = ((lane >> 3) & 1) << 3;

    // fill mapping: 2 threads per row, each 32 halves = 4 x cp16
    const int fr = tid >> 1;
    const int fc = tid & 1;
    const __half* asrc = Xh + (size_t)(row0 + fr) * DMODEL + fc * 32;
    const __half* bsrc = Wz + (size_t)(col0 + fr) * DMODEL + fc * 32;
    const uint32_t fill_off = (fr * GS + fc * 16) * 4;

    float acc[2][8][4] = {};

    const int NKT = DMODEL / 64;   // 12

    // prologue: fill tiles 0 and 1 into stages 0, 1
    #pragma unroll
    for (int p = 0; p < 2; p++) {
        uint32_t ab = smem_b + p * stage_bytes + fill_off;
        uint32_t bb = ab + GT_W * 4;
        #pragma unroll
        for (int i = 0; i < 4; i++) {
            cp_async16(ab + i * 16, asrc + p * 64 + i * 8);
            cp_async16(bb + i * 16, bsrc + p * 64 + i * 8);
        }
        CP_COMMIT();
    }

    for (int kt = 0; kt < NKT; kt++) {
        if (kt + 1 < NKT) CP_WAIT1(); else CP_WAIT0();
        __syncthreads();   // tile kt visible; all prior reads of stage (kt+2)%3 done

        if (kt + 2 < NKT) {
            uint32_t ab = smem_b + ((kt + 2) % GSTAGES) * stage_bytes + fill_off;
            uint32_t bb = ab + GT_W * 4;
            int koff = (kt + 2) * 64;
            #pragma unroll
            for (int i = 0; i < 4; i++) {
                cp_async16(ab + i * 16, asrc + koff + i * 8);
                cp_async16(bb + i * 16, bsrc + koff + i * 8);
            }
            CP_COMMIT();
        }

        const uint32_t astg_b = smem_b + (kt % GSTAGES) * stage_bytes;
        const uint32_t bstg_b = astg_b + GT_W * 4;

        #pragma unroll
        for (int ks = 0; ks < 4; ks++) {
            unsigned a[2][4];
            #pragma unroll
            for (int mi = 0; mi < 2; mi++) {
                uint32_t addr = astg_b + ((wm + mi * 16 + arow) * GS) * 4
                              + (ks * 16 + acol8) * 2;
                ldsm_x4(a[mi], addr);
            }
            #pragma unroll
            for (int jb = 0; jb < 4; jb++) {
                unsigned bb4[4];
                uint32_t addr = bstg_b + ((wn + jb * 16 + krow) * GS) * 4
                              + (ks * 16 + kcol8) * 2;
                ldsm_x4(bb4, addr);
                mma_f16(acc[0][jb * 2], a[0], bb4);
                mma_f16(acc[1][jb * 2], a[1], bb4);
                mma_f16(acc[0][jb * 2 + 1], a[0], bb4 + 2);
                mma_f16(acc[1][jb * 2 + 1], a[1], bb4 + 2);
            }
        }
        // no trailing barrier: next iter's top barrier orders reads vs refill
    }

    const int g = lane >> 2;
    const int tig = lane & 3;
    #pragma unroll
    for (int mi = 0; mi < 2; mi++) {
        int r0 = row0 + wm + mi * 16 + g;
        #pragma unroll
        for (int ni = 0; ni < 8; ni++) {
            int col = col0 + wn + ni * 8 + 2 * tig;
            float2 bb = *(const float2*)&bias[col];
            unsigned lo = packh2((acc[mi][ni][0] + bb.x) * scale,
                                 (acc[mi][ni][1] + bb.y) * scale);
            unsigned hi = packh2((acc[mi][ni][2] + bb.x) * scale,
                                 (acc[mi][ni][3] + bb.y) * scale);
            *(unsigned*)&out[(size_t)r0 * DMODEL + col] = lo;
            *(unsigned*)&out[(size_t)(r0 + 8) * DMODEL + col] = hi;
        }
    }
}

// ---------------------------------------------------------------------------
// Attention v6: j-half interleaved S->ex2->PV (breaks the phase serialization
// that capped tensor at 54%). fp16-frag softmax, tensor-core rowsum, 2 CTA/SM,
// 3-stage cp.async, one barrier per tile.
// CTA = 256 q-rows, 64-col k-tiles, 8 warps x (32q x 64k).
// ---------------------------------------------------------------------------
#define AQ 256
#define QS_W (AQ * GS)
#define KS_W (64 * GS)
#define ASTAGES 3
#define ATTN_SMEM_W (QS_W + ASTAGES * 2 * KS_W)

#define ONES_H2 0x3C003C00u   // half2(1.0, 1.0)

__global__ __launch_bounds__(256, 2) void attn_h(
    const __half* __restrict__ Q, const __half* __restrict__ K,
    const __half* __restrict__ V, float* __restrict__ O)
{
    extern __shared__ unsigned asmem[];
    unsigned* QsW = asmem;

    const uint32_t smem_b = (uint32_t)__cvta_generic_to_shared(asmem);
    const uint32_t kv0_b = smem_b + QS_W * 4;
    const uint32_t stage_bytes = 2 * KS_W * 4;

    const int tid = threadIdx.x;
    const int lane = tid & 31;
    const int w = tid >> 5;
    const int wq = w * 32;
    const int qbase = blockIdx.x * AQ;
    const int h = blockIdx.y;
    const int bn = blockIdx.z;
    const int b = bn / NSRC;
    const int n = bn % NSRC;

    const int krow = (lane & 7) + ((lane >> 4) << 3);
    const int kcol8 = ((lane >> 3) & 1) << 3;
    const int arow = (lane & 15);
    const int acol8 = (lane >> 4) << 3;

    // ---- fill Q: one token row per thread (64 halves = 8 uint4)
    {
        const __half* qsrc = Q + (size_t)(b * SEQ + qbase + tid) * DMODEL + h * DHEAD;
        #pragma unroll
        for (int i = 0; i < 8; i++)
            *(uint4*)&QsW[tid * GS + i * 4] = *(const uint4*)(qsrc + i * 8);
    }

    // ---- cp.async fill helpers
    const size_t kvbase = (size_t)(n * BATCH + b) * SEQ * DMODEL;
    const int fj = tid & 63;
    const int fdc = tid >> 6;
    const __half* kptr = K + kvbase + (size_t)fj * DMODEL + h * DHEAD + fdc * 16;
    const __half* vptr = V + kvbase + (size_t)fj * DMODEL + h * DHEAD + fdc * 16;
    const uint32_t fill_off = (fj * GS + fdc * 8) * 4;

    const int NT = SEQ / 64;

    // prologue: fill tiles 0 and 1 into stages 0, 1
    #pragma unroll
    for (int p = 0; p < 2; p++) {
        size_t off = (size_t)p * 64 * DMODEL;
        uint32_t kd = kv0_b + p * stage_bytes + fill_off;
        uint32_t vd = kd + KS_W * 4;
        cp_async16(kd, kptr + off);
        cp_async16(kd + 16, kptr + off + 8);
        cp_async16(vd, vptr + off);
        cp_async16(vd + 16, vptr + off + 8);
        CP_COMMIT();
    }

    float o[2][8][4] = {};
    float rs[2][4] = {};

    const unsigned ones[2] = {ONES_H2, ONES_H2};

    for (int kt = 0; kt < NT; kt++) {
        if (kt + 1 < NT) CP_WAIT1(); else CP_WAIT0();
        __syncthreads();   // tile kt + Q visible; prior reads of stage (kt+2)%3 done

        if (kt + 2 < NT) {
            size_t off = (size_t)(kt + 2) * 64 * DMODEL;
            uint32_t kd = kv0_b + ((kt + 2) % ASTAGES) * stage_bytes + fill_off;
            uint32_t vd = kd + KS_W * 4;
            cp_async16(kd, kptr + off);
            cp_async16(kd + 16, kptr + off + 8);
            cp_async16(vd, vptr + off);
            cp_async16(vd + 16, vptr + off + 8);
            CP_COMMIT();
        }

        const uint32_t kstg_b = kv0_b + (kt % ASTAGES) * stage_bytes;
        const uint32_t vstg_b = kstg_b + KS_W * 4;

        // ---- two j-halves of 32 k-cols each: S(half) -> ex2 -> rowsum+PV
        #pragma unroll
        for (int jh = 0; jh < 2; jh++) {
            // S for this half: 4 n-frags per mi (2 x 16-col blocks)
            unsigned s[2][4][2] = {};
            #pragma unroll
            for (int ks = 0; ks < 4; ks++) {
                unsigned qa[2][4];
                #pragma unroll
                for (int mi = 0; mi < 2; mi++) {
                    uint32_t qaddr = smem_b + ((wq + mi * 16 + arow) * GS) * 4
                                   + (ks * 16 + acol8) * 2;
                    ldsm_x4(qa[mi], qaddr);
                }
                #pragma unroll
                for (int jb = 0; jb < 2; jb++) {
                    unsigned kb4[4];
                    uint32_t addr = kstg_b + (((jh * 2 + jb) * 16 + krow) * GS) * 4
                                  + (ks * 16 + kcol8) * 2;
                    ldsm_x4(kb4, addr);
                    mma_f16_h(s[0][jb * 2], qa[0], kb4);
                    mma_f16_h(s[1][jb * 2], qa[1], kb4);
                    mma_f16_h(s[0][jb * 2 + 1], qa[0], kb4 + 2);
                    mma_f16_h(s[1][jb * 2 + 1], qa[1], kb4 + 2);
                }
            }

            // ex2 in place (16 regs)
            #pragma unroll
            for (int mi = 0; mi < 2; mi++)
                #pragma unroll
                for (int nf = 0; nf < 4; nf++) {
                    ex2_h2(s[mi][nf][0]);
                    ex2_h2(s[mi][nf][1]);
                }

            // rowsum + PV for the two 16-col k-chunks of this half
            #pragma unroll
            for (int kb = 0; kb < 2; kb++) {
                unsigned pa[2][4];
                #pragma unroll
                for (int mi = 0; mi < 2; mi++) {
                    pa[mi][0] = s[mi][kb * 2][0];
                    pa[mi][1] = s[mi][kb * 2][1];
                    pa[mi][2] = s[mi][kb * 2 + 1][0];
                    pa[mi][3] = s[mi][kb * 2 + 1][1];
                }
                mma_f16(rs[0], pa[0], ones);
                mma_f16(rs[1], pa[1], ones);
                #pragma unroll
                for (int db = 0; db < 4; db++) {
                    unsigned vb4[4];
                    uint32_t addr = vstg_b + (((jh * 2 + kb) * 16 + arow) * GS) * 4
                                  + (db * 16 + acol8) * 2;
                    ldsm_x4_t(vb4, addr);
                    mma_f16(o[0][db * 2], pa[0], vb4);
                    mma_f16(o[1][db * 2], pa[1], vb4);
                    mma_f16(o[0][db * 2 + 1], pa[0], vb4 + 2);
                    mma_f16(o[1][db * 2 + 1], pa[1], vb4 + 2);
                }
            }
        }
        // no trailing barrier
    }

    // ---- normalize + write per-source output (f32)
    const int g = lane >> 2;
    const int tig = lane & 3;
    const size_t obase = (size_t)(n * BATCH + b) * SEQ * DMODEL;
    #pragma unroll
    for (int mi = 0; mi < 2; mi++) {
        float rl0 = 1.f / rs[mi][0];
        float rl1 = 1.f / rs[mi][2];
        int tok = qbase + wq + mi * 16 + g;
        #pragma unroll
        for (int nd = 0; nd < 8; nd++) {
            int col = h * DHEAD + nd * 8 + 2 * tig;
            float2 o0 = make_float2(o[mi][nd][0] * rl0, o[mi][nd][1] * rl0);
            float2 o1 = make_float2(o[mi][nd][2] * rl1, o[mi][nd][3] * rl1);
            *(float2*)&O[obase + (size_t)tok * DMODEL + col] = o0;
            *(float2*)&O[obase + (size_t)(tok + 8) * DMODEL + col] = o1;
        }
    }
}

// ---------------------------------------------------------------------------
__global__ void reduce_sources(const float* __restrict__ gO, float* __restrict__ out)
{
    const size_t stride = (size_t)QROWS * DMODEL;
    size_t i = ((size_t)blockIdx.x * blockDim.x + threadIdx.x) * 4;
    if (i >= stride) return;
    float4 a = *(const float4*)&gO[i];
    #pragma unroll
    for (int n = 1; n < NSRC; n++) {
        float4 c = *(const float4*)&gO[n * stride + i];
        a.x += c.x; a.y += c.y; a.z += c.z; a.w += c.w;
    }
    *(float4*)&out[i] = a;
}

// ---------------------------------------------------------------------------
extern "C" void kernel_launch(void* const* d_in, const int* in_sizes, int n_in,
                              void* d_out, int out_size)
{
    (void)in_sizes; (void)n_in; (void)out_size;
    const float* X  = (const float*)d_in[0];
    const float* Wq = (const float*)d_in[1];
    const float* bq = (const float*)d_in[2];
    const float* Wk = (const float*)d_in[3];
    const float* bk = (const float*)d_in[4];
    const float* Wv = (const float*)d_in[5];
    const float* bv = (const float*)d_in[6];
    float* out = (float*)d_out;

    __half *Xh, *Wt, *Qh, *Kh, *Vh;
    float* Ob;
    cudaGetSymbolAddress((void**)&Xh, g_Xh);
    cudaGetSymbolAddress((void**)&Wt, g_Wt);
    cudaGetSymbolAddress((void**)&Qh, g_Qh);
    cudaGetSymbolAddress((void**)&Kh, g_Kh);
    cudaGetSymbolAddress((void**)&Vh, g_Vh);
    cudaGetSymbolAddress((void**)&Ob, g_O);

    const int gemm_smem = GSTAGES * 2 * GT_W * (int)sizeof(unsigned);  // 110592
    const int attn_smem = ATTN_SMEM_W * (int)sizeof(unsigned);         // 92160
    cudaFuncSetAttribute(gemm_h, cudaFuncAttributeMaxDynamicSharedMemorySize, gemm_smem);
    cudaFuncSetAttribute(attn_h, cudaFuncAttributeMaxDynamicSharedMemorySize, attn_smem);

    // prep: X -> half, W -> transposed half
    prep_x<<<(KVROWS * DMODEL) / (4 * 256), 256>>>(X, Xh);
    prep_w<<<dim3(DMODEL / 32, DMODEL / 32, 3), dim3(32, 8)>>>(Wq, Wk, Wv, Wt);

    // fused QKV projections (exact 2112-CTA 1D grid)
    gemm_h<<<2112, 256, gemm_smem>>>(Xh, Wt, bq, bk, bv, Qh, Kh, Vh);

    // attention
    attn_h<<<dim3(SEQ / AQ, NHEAD, BATCH * NSRC), 256, attn_smem>>>(Qh, Kh, Vh, Ob);

    // sum sources
    const size_t total = (size_t)QROWS * DMODEL / 4;
    reduce_sources<<<(unsigned)((total + 255) / 256), 256>>>(Ob, out);
}

// round 16
// speedup vs baseline: 1.0202x; 1.0202x over previous
#include <cuda_runtime.h>
#include <cuda_fp16.h>
#include <math.h>
#include <stdint.h>

// Problem constants
#define NSRC 5
#define BATCH 4
#define SEQ 1024
#define DMODEL 768
#define NHEAD 12
#define DHEAD 64

#define QROWS 4096      // B*S
#define KVROWS 20480    // N*B*S

// scale folded into Q projection: 1/sqrt(64) * log2(e)  (softmax done in exp2)
#define QSCALE (0.125f * 1.4426950408889634f)

// Scratch (allocation-free rules: __device__ globals)
__device__ __half g_Xh[(size_t)KVROWS * DMODEL];             // X as fp16
__device__ __half g_Wt[3][(size_t)DMODEL * DMODEL];          // W^T as fp16 [n][k]
__device__ __half g_Qh[(size_t)QROWS * DMODEL];              // Q (pre-scaled)
__device__ __half g_Kh[(size_t)KVROWS * DMODEL];
__device__ __half g_Vh[(size_t)KVROWS * DMODEL];
__device__ __half g_O[(size_t)NSRC * QROWS * DMODEL];        // per-source outputs (fp16)

// ---------------------------------------------------------------------------
// fp16 m16n8k16, f32 accum. Layouts (g=lane>>2, tig=lane&3):
//   A: a0={(g,2tig),(g,2tig+1)} a1={(g+8,..)} a2={(g,2tig+8..)} a3={(g+8,2tig+8..)}
//   B: b0={(k=2tig,n=g),(k=2tig+1,n=g)} b1={(k=2tig+8..)}
//   C: c0=(g,2tig) c1=(g,2tig+1) c2=(g+8,2tig) c3=(g+8,2tig+1)
__device__ __forceinline__ void mma_f16(float* c, const unsigned* a, const unsigned* b) {
    asm volatile(
        "mma.sync.aligned.m16n8k16.row.col.f32.f16.f16.f32 "
        "{%0,%1,%2,%3}, {%4,%5,%6,%7}, {%8,%9}, {%0,%1,%2,%3};"
        : "+f"(c[0]), "+f"(c[1]), "+f"(c[2]), "+f"(c[3])
        : "r"(a[0]), "r"(a[1]), "r"(a[2]), "r"(a[3]), "r"(b[0]), "r"(b[1]));
}

// fp16 accumulate variant: C packed f16x2, c0={(g,2tig),(g,2tig+1)},
// c1={(g+8,2tig),(g+8,2tig+1)}  (== PV A-frag layout pairing)
__device__ __forceinline__ void mma_f16_h(unsigned* c, const unsigned* a, const unsigned* b) {
    asm volatile(
        "mma.sync.aligned.m16n8k16.row.col.f16.f16.f16.f16 "
        "{%0,%1}, {%2,%3,%4,%5}, {%6,%7}, {%0,%1};"
        : "+r"(c[0]), "+r"(c[1])
        : "r"(a[0]), "r"(a[1]), "r"(a[2]), "r"(a[3]), "r"(b[0]), "r"(b[1]));
}

// packed half2 exp2 (in place)
__device__ __forceinline__ void ex2_h2(unsigned& x) {
    asm("ex2.approx.f16x2 %0, %0;" : "+r"(x));
}

// ldmatrix x4: output reg i <- 8x8 matrix whose row addresses come from
// lanes [8i, 8i+8). Lane-addressing determines the matrix->reg pairing.
__device__ __forceinline__ void ldsm_x4(unsigned* r, uint32_t addr) {
    asm volatile("ldmatrix.sync.aligned.m8n8.x4.shared.b16 {%0,%1,%2,%3}, [%4];"
        : "=r"(r[0]), "=r"(r[1]), "=r"(r[2]), "=r"(r[3]) : "r"(addr));
}
__device__ __forceinline__ void ldsm_x4_t(unsigned* r, uint32_t addr) {
    asm volatile("ldmatrix.sync.aligned.m8n8.x4.trans.shared.b16 {%0,%1,%2,%3}, [%4];"
        : "=r"(r[0]), "=r"(r[1]), "=r"(r[2]), "=r"(r[3]) : "r"(addr));
}

__device__ __forceinline__ void cp_async16(uint32_t dst, const void* src) {
    asm volatile("cp.async.cg.shared.global [%0], [%1], 16;" :: "r"(dst), "l"(src));
}
#define CP_COMMIT() asm volatile("cp.async.commit_group;")
#define CP_WAIT1()  asm volatile("cp.async.wait_group 1;")
#define CP_WAIT0()  asm volatile("cp.async.wait_group 0;")

__device__ __forceinline__ unsigned packh2(float lo, float hi) {
    __half2 h = __floats2half2_rn(lo, hi);
    return *(unsigned*)&h;
}

// ---------------------------------------------------------------------------
// prep_x: fp32 -> fp16 conversion of X
// ---------------------------------------------------------------------------
__global__ void prep_x(const float* __restrict__ X, __half* __restrict__ Xh)
{
    size_t i = ((size_t)blockIdx.x * blockDim.x + threadIdx.x) * 4;
    float4 v = *(const float4*)&X[i];
    __half2 h0 = __floats2half2_rn(v.x, v.y);
    __half2 h1 = __floats2half2_rn(v.z, v.w);
    uint2 u;
    u.x = *(unsigned*)&h0; u.y = *(unsigned*)&h1;
    *(uint2*)&Xh[i] = u;
}

// ---------------------------------------------------------------------------
// prep_w: transpose + convert Wq/Wk/Wv [k][n] f32 -> Wt[z][n][k] fp16
// ---------------------------------------------------------------------------
__global__ void prep_w(const float* __restrict__ Wq, const float* __restrict__ Wk,
                       const float* __restrict__ Wv, __half* __restrict__ Wt)
{
    __shared__ float tile[32][33];
    const float* W = (blockIdx.z == 0) ? Wq : (blockIdx.z == 1) ? Wk : Wv;
    __half* out = Wt + (size_t)blockIdx.z * DMODEL * DMODEL;
    int k0 = blockIdx.y * 32, n0 = blockIdx.x * 32;
    int tx = threadIdx.x, ty = threadIdx.y;
    #pragma unroll
    for (int i = 0; i < 4; i++)
        tile[ty + i * 8][tx] = W[(size_t)(k0 + ty + i * 8) * DMODEL + n0 + tx];
    __syncthreads();
    #pragma unroll
    for (int i = 0; i < 4; i++)
        out[(size_t)(n0 + ty + i * 8) * DMODEL + k0 + tx] =
            __float2half(tile[tx][ty + i * 8]);
}

// ---------------------------------------------------------------------------
// Fused QKV GEMM v3 (fp16 mma, ldmatrix + 3-stage cp.async, ONE barrier/iter)
// C = Xh @ Wt^T + bias, z selects {Q,K,V}.
// CTA 128m x 128n, BK=64, 8 warps of 32m x 64n. Row stride 36 words.
// ---------------------------------------------------------------------------
#define GS 36   // word stride (144B): ldmatrix rows hit 8 distinct 16B banks
#define GT_W (128 * GS)
#define GSTAGES 3

__global__ __launch_bounds__(256, 2) void gemm_h(
    const __half* __restrict__ Xh, const __half* __restrict__ Wt,
    const float* __restrict__ bq, const float* __restrict__ bk,
    const float* __restrict__ bv,
    __half* __restrict__ Qo, __half* __restrict__ Ko, __half* __restrict__ Vo)
{
    const int z = blockIdx.z;
    if (z == 0 && blockIdx.y >= QROWS / 128) return;

    extern __shared__ unsigned gsm[];
    const uint32_t smem_b = (uint32_t)__cvta_generic_to_shared(gsm);
    const uint32_t stage_bytes = 2 * GT_W * 4;

    const __half* Wz = Wt + (size_t)z * DMODEL * DMODEL;
    const float* bias = (z == 0) ? bq : (z == 1) ? bk : bv;
    __half* out = (z == 0) ? Qo : (z == 1) ? Ko : Vo;
    const float scale = (z == 0) ? QSCALE : 1.0f;

    const int tid = threadIdx.x;
    const int lane = tid & 31;
    const int w = tid >> 5;
    const int wm = (w & 3) * 32;
    const int wn = (w >> 2) * 64;
    const int row0 = blockIdx.y * 128;
    const int col0 = blockIdx.x * 128;

    // A-operand (row varies first):
    const int arow = (lane & 15);
    const int acol8 = (lane >> 4) << 3;
    // B-operand non-trans (col-half varies before row-half):
    const int krow = (lane & 7) + ((lane >> 4) << 3);
    const int kcol8 = ((lane >> 3) & 1) << 3;

    // fill mapping: 2 threads per row, each 32 halves = 4 x cp16
    const int fr = tid >> 1;
    const int fc = tid & 1;
    const __half* asrc = Xh + (size_t)(row0 + fr) * DMODEL + fc * 32;
    const __half* bsrc = Wz + (size_t)(col0 + fr) * DMODEL + fc * 32;
    const uint32_t fill_off = (fr * GS + fc * 16) * 4;

    float acc[2][8][4] = {};

    const int NKT = DMODEL / 64;   // 12

    // prologue: fill tiles 0 and 1 into stages 0, 1
    #pragma unroll
    for (int p = 0; p < 2; p++) {
        uint32_t ab = smem_b + p * stage_bytes + fill_off;
        uint32_t bb = ab + GT_W * 4;
        #pragma unroll
        for (int i = 0; i < 4; i++) {
            cp_async16(ab + i * 16, asrc + p * 64 + i * 8);
            cp_async16(bb + i * 16, bsrc + p * 64 + i * 8);
        }
        CP_COMMIT();
    }

    for (int kt = 0; kt < NKT; kt++) {
        if (kt + 1 < NKT) CP_WAIT1(); else CP_WAIT0();
        __syncthreads();   // tile kt visible; all prior reads of stage (kt+2)%3 done

        if (kt + 2 < NKT) {
            uint32_t ab = smem_b + ((kt + 2) % GSTAGES) * stage_bytes + fill_off;
            uint32_t bb = ab + GT_W * 4;
            int koff = (kt + 2) * 64;
            #pragma unroll
            for (int i = 0; i < 4; i++) {
                cp_async16(ab + i * 16, asrc + koff + i * 8);
                cp_async16(bb + i * 16, bsrc + koff + i * 8);
            }
            CP_COMMIT();
        }

        const uint32_t astg_b = smem_b + (kt % GSTAGES) * stage_bytes;
        const uint32_t bstg_b = astg_b + GT_W * 4;

        #pragma unroll
        for (int ks = 0; ks < 4; ks++) {
            unsigned a[2][4];
            #pragma unroll
            for (int mi = 0; mi < 2; mi++) {
                uint32_t addr = astg_b + ((wm + mi * 16 + arow) * GS) * 4
                              + (ks * 16 + acol8) * 2;
                ldsm_x4(a[mi], addr);
            }
            #pragma unroll
            for (int jb = 0; jb < 4; jb++) {
                unsigned bb4[4];
                uint32_t addr = bstg_b + ((wn + jb * 16 + krow) * GS) * 4
                              + (ks * 16 + kcol8) * 2;
                ldsm_x4(bb4, addr);
                mma_f16(acc[0][jb * 2], a[0], bb4);
                mma_f16(acc[1][jb * 2], a[1], bb4);
                mma_f16(acc[0][jb * 2 + 1], a[0], bb4 + 2);
                mma_f16(acc[1][jb * 2 + 1], a[1], bb4 + 2);
            }
        }
        // no trailing barrier: next iter's top barrier orders reads vs refill
    }

    const int g = lane >> 2;
    const int tig = lane & 3;
    #pragma unroll
    for (int mi = 0; mi < 2; mi++) {
        int r0 = row0 + wm + mi * 16 + g;
        #pragma unroll
        for (int ni = 0; ni < 8; ni++) {
            int col = col0 + wn + ni * 8 + 2 * tig;
            float2 bb = *(const float2*)&bias[col];
            unsigned lo = packh2((acc[mi][ni][0] + bb.x) * scale,
                                 (acc[mi][ni][1] + bb.y) * scale);
            unsigned hi = packh2((acc[mi][ni][2] + bb.x) * scale,
                                 (acc[mi][ni][3] + bb.y) * scale);
            *(unsigned*)&out[(size_t)r0 * DMODEL + col] = lo;
            *(unsigned*)&out[(size_t)(r0 + 8) * DMODEL + col] = hi;
        }
    }
}

// ---------------------------------------------------------------------------
// Attention v5 (R13-best): fp16-frag softmax, tensor-core rowsum, 2 CTAs/SM,
// 3-stage cp.async pipeline with ONE barrier per tile. fp16 output.
// CTA = 256 q-rows, 64-col k-tiles, 8 warps x (32q x 64k).
// ---------------------------------------------------------------------------
#define AQ 256
#define QS_W (AQ * GS)
#define KS_W (64 * GS)
#define ASTAGES 3
#define ATTN_SMEM_W (QS_W + ASTAGES * 2 * KS_W)

#define ONES_H2 0x3C003C00u   // half2(1.0, 1.0)

__global__ __launch_bounds__(256, 2) void attn_h(
    const __half* __restrict__ Q, const __half* __restrict__ K,
    const __half* __restrict__ V, __half* __restrict__ O)
{
    extern __shared__ unsigned asmem[];
    unsigned* QsW = asmem;

    const uint32_t smem_b = (uint32_t)__cvta_generic_to_shared(asmem);
    const uint32_t kv0_b = smem_b + QS_W * 4;
    const uint32_t stage_bytes = 2 * KS_W * 4;

    const int tid = threadIdx.x;
    const int lane = tid & 31;
    const int w = tid >> 5;
    const int wq = w * 32;
    const int qbase = blockIdx.x * AQ;
    const int h = blockIdx.y;
    const int bn = blockIdx.z;
    const int b = bn / NSRC;
    const int n = bn % NSRC;

    const int krow = (lane & 7) + ((lane >> 4) << 3);
    const int kcol8 = ((lane >> 3) & 1) << 3;
    const int arow = (lane & 15);
    const int acol8 = (lane >> 4) << 3;

    // ---- fill Q: one token row per thread (64 halves = 8 uint4)
    {
        const __half* qsrc = Q + (size_t)(b * SEQ + qbase + tid) * DMODEL + h * DHEAD;
        #pragma unroll
        for (int i = 0; i < 8; i++)
            *(uint4*)&QsW[tid * GS + i * 4] = *(const uint4*)(qsrc + i * 8);
    }

    // ---- cp.async fill helpers
    const size_t kvbase = (size_t)(n * BATCH + b) * SEQ * DMODEL;
    const int fj = tid & 63;
    const int fdc = tid >> 6;
    const __half* kptr = K + kvbase + (size_t)fj * DMODEL + h * DHEAD + fdc * 16;
    const __half* vptr = V + kvbase + (size_t)fj * DMODEL + h * DHEAD + fdc * 16;
    const uint32_t fill_off = (fj * GS + fdc * 8) * 4;

    const int NT = SEQ / 64;

    // prologue: fill tiles 0 and 1 into stages 0, 1
    #pragma unroll
    for (int p = 0; p < 2; p++) {
        size_t off = (size_t)p * 64 * DMODEL;
        uint32_t kd = kv0_b + p * stage_bytes + fill_off;
        uint32_t vd = kd + KS_W * 4;
        cp_async16(kd, kptr + off);
        cp_async16(kd + 16, kptr + off + 8);
        cp_async16(vd, vptr + off);
        cp_async16(vd + 16, vptr + off + 8);
        CP_COMMIT();
    }

    float o[2][8][4] = {};
    float rs[2][4] = {};

    const unsigned ones[2] = {ONES_H2, ONES_H2};

    for (int kt = 0; kt < NT; kt++) {
        if (kt + 1 < NT) CP_WAIT1(); else CP_WAIT0();
        __syncthreads();   // tile kt + Q visible; prior reads of stage (kt+2)%3 done

        if (kt + 2 < NT) {
            size_t off = (size_t)(kt + 2) * 64 * DMODEL;
            uint32_t kd = kv0_b + ((kt + 2) % ASTAGES) * stage_bytes + fill_off;
            uint32_t vd = kd + KS_W * 4;
            cp_async16(kd, kptr + off);
            cp_async16(kd + 16, kptr + off + 8);
            cp_async16(vd, vptr + off);
            cp_async16(vd + 16, vptr + off + 8);
            CP_COMMIT();
        }

        const uint32_t kstg_b = kv0_b + (kt % ASTAGES) * stage_bytes;
        const uint32_t vstg_b = kstg_b + KS_W * 4;

        // ---- S = Qs @ Ks^T into packed fp16 frags
        unsigned s[2][8][2] = {};
        #pragma unroll
        for (int ks = 0; ks < 4; ks++) {
            unsigned qa[2][4];
            #pragma unroll
            for (int mi = 0; mi < 2; mi++) {
                uint32_t qaddr = smem_b + ((wq + mi * 16 + arow) * GS) * 4
                               + (ks * 16 + acol8) * 2;
                ldsm_x4(qa[mi], qaddr);
            }
            #pragma unroll
            for (int jb = 0; jb < 4; jb++) {
                unsigned kb4[4];
                uint32_t addr = kstg_b + ((jb * 16 + krow) * GS) * 4
                              + (ks * 16 + kcol8) * 2;
                ldsm_x4(kb4, addr);
                mma_f16_h(s[0][jb * 2], qa[0], kb4);
                mma_f16_h(s[1][jb * 2], qa[1], kb4);
                mma_f16_h(s[0][jb * 2 + 1], qa[0], kb4 + 2);
                mma_f16_h(s[1][jb * 2 + 1], qa[1], kb4 + 2);
            }
        }

        // ---- P = exp2(S) in place
        #pragma unroll
        for (int mi = 0; mi < 2; mi++)
            #pragma unroll
            for (int ni = 0; ni < 8; ni++) {
                ex2_h2(s[mi][ni][0]);
                ex2_h2(s[mi][ni][1]);
            }

        // ---- rowsum += P @ ones, O += P @ V
        #pragma unroll
        for (int kb = 0; kb < 4; kb++) {
            unsigned pa[2][4];
            #pragma unroll
            for (int mi = 0; mi < 2; mi++) {
                pa[mi][0] = s[mi][kb * 2][0];
                pa[mi][1] = s[mi][kb * 2][1];
                pa[mi][2] = s[mi][kb * 2 + 1][0];
                pa[mi][3] = s[mi][kb * 2 + 1][1];
            }
            mma_f16(rs[0], pa[0], ones);
            mma_f16(rs[1], pa[1], ones);
            #pragma unroll
            for (int db = 0; db < 4; db++) {
                unsigned vb4[4];
                uint32_t addr = vstg_b + ((kb * 16 + arow) * GS) * 4
                              + (db * 16 + acol8) * 2;
                ldsm_x4_t(vb4, addr);
                mma_f16(o[0][db * 2], pa[0], vb4);
                mma_f16(o[1][db * 2], pa[1], vb4);
                mma_f16(o[0][db * 2 + 1], pa[0], vb4 + 2);
                mma_f16(o[1][db * 2 + 1], pa[1], vb4 + 2);
            }
        }
        // no trailing barrier
    }

    // ---- normalize + write per-source output (fp16 packed)
    const int g = lane >> 2;
    const int tig = lane & 3;
    const size_t obase = (size_t)(n * BATCH + b) * SEQ * DMODEL;
    #pragma unroll
    for (int mi = 0; mi < 2; mi++) {
        float rl0 = 1.f / rs[mi][0];
        float rl1 = 1.f / rs[mi][2];
        int tok = qbase + wq + mi * 16 + g;
        #pragma unroll
        for (int nd = 0; nd < 8; nd++) {
            int col = h * DHEAD + nd * 8 + 2 * tig;
            unsigned p0 = packh2(o[mi][nd][0] * rl0, o[mi][nd][1] * rl0);
            unsigned p1 = packh2(o[mi][nd][2] * rl1, o[mi][nd][3] * rl1);
            *(unsigned*)&O[obase + (size_t)tok * DMODEL + col] = p0;
            *(unsigned*)&O[obase + (size_t)(tok + 8) * DMODEL + col] = p1;
        }
    }
}

// ---------------------------------------------------------------------------
// Sum 5 per-source fp16 outputs into final f32 out (deterministic order)
// ---------------------------------------------------------------------------
__global__ void reduce_sources(const __half* __restrict__ gO, float* __restrict__ out)
{
    const size_t stride = (size_t)QROWS * DMODEL;
    size_t i = ((size_t)blockIdx.x * blockDim.x + threadIdx.x) * 4;
    if (i >= stride) return;
    float a0 = 0.f, a1 = 0.f, a2 = 0.f, a3 = 0.f;
    #pragma unroll
    for (int n = 0; n < NSRC; n++) {
        uint2 u = *(const uint2*)&gO[n * stride + i];
        __half2 h0 = *(__half2*)&u.x;
        __half2 h1 = *(__half2*)&u.y;
        float2 f0 = __half22float2(h0);
        float2 f1 = __half22float2(h1);
        a0 += f0.x; a1 += f0.y; a2 += f1.x; a3 += f1.y;
    }
    float4 r;
    r.x = a0; r.y = a1; r.z = a2; r.w = a3;
    *(float4*)&out[i] = r;
}

// ---------------------------------------------------------------------------
extern "C" void kernel_launch(void* const* d_in, const int* in_sizes, int n_in,
                              void* d_out, int out_size)
{
    (void)in_sizes; (void)n_in; (void)out_size;
    const float* X  = (const float*)d_in[0];
    const float* Wq = (const float*)d_in[1];
    const float* bq = (const float*)d_in[2];
    const float* Wk = (const float*)d_in[3];
    const float* bk = (const float*)d_in[4];
    const float* Wv = (const float*)d_in[5];
    const float* bv = (const float*)d_in[6];
    float* out = (float*)d_out;

    __half *Xh, *Wt, *Qh, *Kh, *Vh, *Ob;
    cudaGetSymbolAddress((void**)&Xh, g_Xh);
    cudaGetSymbolAddress((void**)&Wt, g_Wt);
    cudaGetSymbolAddress((void**)&Qh, g_Qh);
    cudaGetSymbolAddress((void**)&Kh, g_Kh);
    cudaGetSymbolAddress((void**)&Vh, g_Vh);
    cudaGetSymbolAddress((void**)&Ob, g_O);

    const int gemm_smem = GSTAGES * 2 * GT_W * (int)sizeof(unsigned);  // 110592
    const int attn_smem = ATTN_SMEM_W * (int)sizeof(unsigned);         // 92160
    cudaFuncSetAttribute(gemm_h, cudaFuncAttributeMaxDynamicSharedMemorySize, gemm_smem);
    cudaFuncSetAttribute(attn_h, cudaFuncAttributeMaxDynamicSharedMemorySize, attn_smem);

    // prep: X -> half, W -> transposed half
    prep_x<<<(KVROWS * DMODEL) / (4 * 256), 256>>>(X, Xh);
    prep_w<<<dim3(DMODEL / 32, DMODEL / 32, 3), dim3(32, 8)>>>(Wq, Wk, Wv, Wt);

    // fused QKV projections
    gemm_h<<<dim3(DMODEL / 128, KVROWS / 128, 3), 256, gemm_smem>>>(
        Xh, Wt, bq, bk, bv, Qh, Kh, Vh);

    // attention
    attn_h<<<dim3(SEQ / AQ, NHEAD, BATCH * NSRC), 256, attn_smem>>>(Qh, Kh, Vh, Ob);

    // sum sources
    const size_t total = (size_t)QROWS * DMODEL / 4;
    reduce_sources<<<(unsigned)((total + 255) / 256), 256>>>(Ob, out);
}